// round 5
// baseline (speedup 1.0000x reference)
#include <cuda_runtime.h>

#define BATCH 32
#define CDIM  256
#define LDIM  1024

// Scratch: softmax probabilities P[B][L][L] fp32 (128 MiB) + dense bias [L][L].
__device__ float d_P[(size_t)BATCH * LDIM * LDIM];
__device__ float d_bias[(size_t)LDIM * LDIM];

// ---------------------------------------------------------------------------
// tf32 mma.sync helpers
// ---------------------------------------------------------------------------
__device__ __forceinline__ void mma8(float* c,
                                     unsigned a0, unsigned a1, unsigned a2, unsigned a3,
                                     unsigned b0, unsigned b1) {
    asm volatile(
        "mma.sync.aligned.m16n8k8.row.col.f32.tf32.tf32.f32 "
        "{%0,%1,%2,%3}, {%4,%5,%6,%7}, {%8,%9}, {%0,%1,%2,%3};\n"
        : "+f"(c[0]), "+f"(c[1]), "+f"(c[2]), "+f"(c[3])
        : "r"(a0), "r"(a1), "r"(a2), "r"(a3), "r"(b0), "r"(b1));
}

__device__ __forceinline__ unsigned tf32_hi(float x) {
    return __float_as_uint(x) & 0xffffe000u;
}
__device__ __forceinline__ unsigned tf32_lo(float x, unsigned hi) {
    return __float_as_uint(x - __uint_as_float(hi));
}
__device__ __forceinline__ unsigned tf32_rna(float x) {
    unsigned r;
    asm("cvt.rna.tf32.f32 %0, %1;" : "=r"(r) : "f"(x));
    return r;
}

// ---------------------------------------------------------------------------
// Kernel 0: expand bias_table[rel_index] -> dense [L,L]
// ---------------------------------------------------------------------------
__global__ void bias_kernel(const float* __restrict__ table,
                            const int* __restrict__ ridx) {
    int i = blockIdx.x * blockDim.x + threadIdx.x;
    d_bias[i] = table[ridx[i]];
}

// ---------------------------------------------------------------------------
// Kernel 1: scores = Q^T K + bias (tf32x3 split), softmax over j, write P.
// CTA: 32 i-rows x 1024 j (full row). 512 threads = 16 warps.
// Warp tile: 32i x 64j = 2 i-tiles x 8 j-tiles of m16n8. C chunked by 32.
// smem: ks[32][1032] (pad so B-frag LDS conflict-free), qs[32][36].
// ---------------------------------------------------------------------------
#define T1 512
#define KSTRIDE 1032
#define QSTRIDE 36

__global__ void __launch_bounds__(T1)
scores_mma_kernel(const float* __restrict__ q, const float* __restrict__ k) {
    extern __shared__ float smem[];
    float* ks  = smem;                       // [32][1032]
    float* qs  = smem + 32 * KSTRIDE;        // [32][36]
    float* red = qs + 32 * QSTRIDE;          // [32][16]

    const int b    = blockIdx.y;
    const int i0   = blockIdx.x * 32;
    const int tid  = threadIdx.x;
    const int warp = tid >> 5;
    const int lane = tid & 31;
    const int g    = lane >> 2;              // group row 0..7
    const int tig  = lane & 3;               // thread-in-group
    const int j0w  = warp * 64;

    const float* qb = q + (size_t)b * CDIM * LDIM;
    const float* kb = k + (size_t)b * CDIM * LDIM;

    float acc[2][8][4];
#pragma unroll
    for (int it = 0; it < 2; it++)
#pragma unroll
        for (int jt = 0; jt < 8; jt++)
#pragma unroll
            for (int f = 0; f < 4; f++) acc[it][jt][f] = 0.f;

    for (int c0 = 0; c0 < CDIM; c0 += 32) {
        // K chunk [32][1024] -> ks, coalesced float4
#pragma unroll
        for (int t = 0; t < 16; t++) {
            int idx = tid + t * T1;
            int row = idx >> 8;
            int col = (idx & 255) << 2;
            *(float4*)(ks + row * KSTRIDE + col) =
                *(const float4*)(kb + (size_t)(c0 + row) * LDIM + col);
        }
        // Q chunk: qs[r][cc] = q[c0+cc][i0+r]
#pragma unroll
        for (int t = 0; t < 2; t++) {
            int idx = tid + t * T1;
            int cc = idx >> 5;
            int r  = idx & 31;
            qs[r * QSTRIDE + cc] = qb[(size_t)(c0 + cc) * LDIM + i0 + r];
        }
        __syncthreads();

#pragma unroll
        for (int kk = 0; kk < 32; kk += 8) {
            // A fragments (hi/lo split)
            unsigned ah[2][4], al[2][4];
#pragma unroll
            for (int it = 0; it < 2; it++) {
                int base = (it * 16 + g) * QSTRIDE + kk + tig;
                float a0 = qs[base];
                float a1 = qs[base + 8 * QSTRIDE];
                float a2 = qs[base + 4];
                float a3 = qs[base + 8 * QSTRIDE + 4];
                ah[it][0] = tf32_hi(a0); al[it][0] = tf32_lo(a0, ah[it][0]);
                ah[it][1] = tf32_hi(a1); al[it][1] = tf32_lo(a1, ah[it][1]);
                ah[it][2] = tf32_hi(a2); al[it][2] = tf32_lo(a2, ah[it][2]);
                ah[it][3] = tf32_hi(a3); al[it][3] = tf32_lo(a3, ah[it][3]);
            }
#pragma unroll
            for (int jt = 0; jt < 8; jt++) {
                int jcol = j0w + jt * 8 + g;
                float b0 = ks[(kk + tig) * KSTRIDE + jcol];
                float b1 = ks[(kk + tig + 4) * KSTRIDE + jcol];
                unsigned bh0 = tf32_hi(b0), bh1 = tf32_hi(b1);
                unsigned bl0 = tf32_lo(b0, bh0), bl1 = tf32_lo(b1, bh1);
#pragma unroll
                for (int it = 0; it < 2; it++) {
                    mma8(acc[it][jt], ah[it][0], ah[it][1], ah[it][2], ah[it][3], bh0, bh1);
                    mma8(acc[it][jt], ah[it][0], ah[it][1], ah[it][2], ah[it][3], bl0, bl1);
                    mma8(acc[it][jt], al[it][0], al[it][1], al[it][2], al[it][3], bh0, bh1);
                }
            }
        }
        __syncthreads();
    }

    // ---- add bias ----
#pragma unroll
    for (int it = 0; it < 2; it++)
#pragma unroll
        for (int rr = 0; rr < 2; rr++) {
            int rowl = it * 16 + g + rr * 8;
            const float* brow = d_bias + (size_t)(i0 + rowl) * LDIM + j0w + 2 * tig;
#pragma unroll
            for (int jt = 0; jt < 8; jt++) {
                float2 bv = *(const float2*)(brow + jt * 8);
                acc[it][jt][rr * 2]     += bv.x;
                acc[it][jt][rr * 2 + 1] += bv.y;
            }
        }

    // ---- row max over full 1024 j (16 warps share rows) ----
    float mrow[2][2];
#pragma unroll
    for (int it = 0; it < 2; it++)
#pragma unroll
        for (int rr = 0; rr < 2; rr++) {
            float m = -3.4e38f;
#pragma unroll
            for (int jt = 0; jt < 8; jt++) {
                m = fmaxf(m, acc[it][jt][rr * 2]);
                m = fmaxf(m, acc[it][jt][rr * 2 + 1]);
            }
            m = fmaxf(m, __shfl_xor_sync(0xffffffffu, m, 1));
            m = fmaxf(m, __shfl_xor_sync(0xffffffffu, m, 2));
            if (tig == 0) red[(it * 16 + g + rr * 8) * 16 + warp] = m;
        }
    __syncthreads();
#pragma unroll
    for (int it = 0; it < 2; it++)
#pragma unroll
        for (int rr = 0; rr < 2; rr++) {
            int rowl = it * 16 + g + rr * 8;
            float m = red[rowl * 16];
#pragma unroll
            for (int w = 1; w < 16; w++) m = fmaxf(m, red[rowl * 16 + w]);
            mrow[it][rr] = m;
        }
    __syncthreads();

    // ---- exp + row sum ----
#pragma unroll
    for (int it = 0; it < 2; it++)
#pragma unroll
        for (int rr = 0; rr < 2; rr++) {
            float s = 0.f;
#pragma unroll
            for (int jt = 0; jt < 8; jt++) {
                float p0 = __expf(acc[it][jt][rr * 2]     - mrow[it][rr]);
                float p1 = __expf(acc[it][jt][rr * 2 + 1] - mrow[it][rr]);
                acc[it][jt][rr * 2]     = p0;
                acc[it][jt][rr * 2 + 1] = p1;
                s += p0 + p1;
            }
            s += __shfl_xor_sync(0xffffffffu, s, 1);
            s += __shfl_xor_sync(0xffffffffu, s, 2);
            if (tig == 0) red[(it * 16 + g + rr * 8) * 16 + warp] = s;
        }
    __syncthreads();

    float* Pb = d_P + ((size_t)b * LDIM + i0) * LDIM;
#pragma unroll
    for (int it = 0; it < 2; it++)
#pragma unroll
        for (int rr = 0; rr < 2; rr++) {
            int rowl = it * 16 + g + rr * 8;
            float s = red[rowl * 16];
#pragma unroll
            for (int w = 1; w < 16; w++) s += red[rowl * 16 + w];
            float inv = 1.0f / s;
            float* prow = Pb + (size_t)rowl * LDIM + j0w + 2 * tig;
#pragma unroll
            for (int jt = 0; jt < 8; jt++) {
                float2 o;
                o.x = acc[it][jt][rr * 2] * inv;
                o.y = acc[it][jt][rr * 2 + 1] * inv;
                *(float2*)(prow + jt * 8) = o;
            }
        }
}

// ---------------------------------------------------------------------------
// Kernel 2: V = P @ v^T, SD = P @ std^T, single-pass tf32 mma.
// CTA tile: 128i x 128c. 512 threads = 16 warps (4 wi x 4 wc).
// Warp tile: 32i x 32c = 2 i-tiles x 4 n-tiles per output.
// Operands pre-converted to tf32 (rna) when staged into smem.
// ---------------------------------------------------------------------------
#define T2 512
#define PSTRIDE 36
#define VSTRIDE 136

__global__ void __launch_bounds__(T2)
out_mma_kernel(const float* __restrict__ v, const float* __restrict__ sd,
               float* __restrict__ out) {
    extern __shared__ float smem2[];
    float* ps = smem2;                        // [128][36]
    float* vs = ps + 128 * PSTRIDE;           // [32][136]
    float* ss = vs + 32 * VSTRIDE;            // [32][136]

    const int b    = blockIdx.z;
    const int i0   = blockIdx.x * 128;
    const int c0   = blockIdx.y * 128;
    const int tid  = threadIdx.x;
    const int warp = tid >> 5;
    const int lane = tid & 31;
    const int g    = lane >> 2;
    const int tig  = lane & 3;
    const int wi   = warp & 3;                // i block of 32
    const int wc   = warp >> 2;               // c block of 32

    const float* Pb = d_P + ((size_t)b * LDIM + i0) * LDIM;
    const float* vb = v  + ((size_t)b * CDIM + c0) * LDIM;
    const float* sb = sd + ((size_t)b * CDIM + c0) * LDIM;

    float aV[2][4][4], aS[2][4][4];
#pragma unroll
    for (int it = 0; it < 2; it++)
#pragma unroll
        for (int nt = 0; nt < 4; nt++)
#pragma unroll
            for (int f = 0; f < 4; f++) { aV[it][nt][f] = 0.f; aS[it][nt][f] = 0.f; }

    for (int j0 = 0; j0 < LDIM; j0 += 32) {
        // P tile 128 x 32 (row-major, pre-cvt to tf32)
#pragma unroll
        for (int t = 0; t < 2; t++) {
            int idx = tid + t * T2;
            int i  = idx >> 3;
            int j4 = (idx & 7) << 2;
            float4 p4 = *(const float4*)(Pb + (size_t)i * LDIM + j0 + j4);
            float* dst = ps + i * PSTRIDE + j4;
            dst[0] = __uint_as_float(tf32_rna(p4.x));
            dst[1] = __uint_as_float(tf32_rna(p4.y));
            dst[2] = __uint_as_float(tf32_rna(p4.z));
            dst[3] = __uint_as_float(tf32_rna(p4.w));
        }
        // v / std tiles 128c x 32j -> transposed [j][c], pre-cvt
#pragma unroll
        for (int t = 0; t < 2; t++) {
            int idx = tid + t * T2;
            int c  = idx >> 3;
            int j4 = (idx & 7) << 2;
            float4 t4 = *(const float4*)(vb + (size_t)c * LDIM + j0 + j4);
            vs[(j4 + 0) * VSTRIDE + c] = __uint_as_float(tf32_rna(t4.x));
            vs[(j4 + 1) * VSTRIDE + c] = __uint_as_float(tf32_rna(t4.y));
            vs[(j4 + 2) * VSTRIDE + c] = __uint_as_float(tf32_rna(t4.z));
            vs[(j4 + 3) * VSTRIDE + c] = __uint_as_float(tf32_rna(t4.w));
            float4 u4 = *(const float4*)(sb + (size_t)c * LDIM + j0 + j4);
            ss[(j4 + 0) * VSTRIDE + c] = __uint_as_float(tf32_rna(u4.x));
            ss[(j4 + 1) * VSTRIDE + c] = __uint_as_float(tf32_rna(u4.y));
            ss[(j4 + 2) * VSTRIDE + c] = __uint_as_float(tf32_rna(u4.z));
            ss[(j4 + 3) * VSTRIDE + c] = __uint_as_float(tf32_rna(u4.w));
        }
        __syncthreads();

#pragma unroll
        for (int kk = 0; kk < 32; kk += 8) {
            unsigned au[2][4];
#pragma unroll
            for (int it = 0; it < 2; it++) {
                int base = (wi * 32 + it * 16 + g) * PSTRIDE + kk + tig;
                au[it][0] = __float_as_uint(ps[base]);
                au[it][1] = __float_as_uint(ps[base + 8 * PSTRIDE]);
                au[it][2] = __float_as_uint(ps[base + 4]);
                au[it][3] = __float_as_uint(ps[base + 8 * PSTRIDE + 4]);
            }
#pragma unroll
            for (int nt = 0; nt < 4; nt++) {
                int ncol = wc * 32 + nt * 8 + g;
                unsigned bv0 = __float_as_uint(vs[(kk + tig) * VSTRIDE + ncol]);
                unsigned bv1 = __float_as_uint(vs[(kk + tig + 4) * VSTRIDE + ncol]);
                unsigned bs0 = __float_as_uint(ss[(kk + tig) * VSTRIDE + ncol]);
                unsigned bs1 = __float_as_uint(ss[(kk + tig + 4) * VSTRIDE + ncol]);
#pragma unroll
                for (int it = 0; it < 2; it++) {
                    mma8(aV[it][nt], au[it][0], au[it][1], au[it][2], au[it][3], bv0, bv1);
                    mma8(aS[it][nt], au[it][0], au[it][1], au[it][2], au[it][3], bs0, bs1);
                }
            }
        }
        __syncthreads();
    }

    // epilogue: out[b][c][i] for V, then SD at +B*C*L
    const size_t base  = (size_t)b * CDIM * LDIM;
    const size_t sdoff = (size_t)BATCH * CDIM * LDIM;
#pragma unroll
    for (int it = 0; it < 2; it++)
#pragma unroll
        for (int nt = 0; nt < 4; nt++)
#pragma unroll
            for (int rr = 0; rr < 2; rr++) {
                int i = i0 + wi * 32 + it * 16 + g + rr * 8;
#pragma unroll
                for (int ff = 0; ff < 2; ff++) {
                    int c = c0 + wc * 32 + nt * 8 + 2 * tig + ff;
                    size_t o = base + (size_t)c * LDIM + i;
                    out[o]         = aV[it][nt][rr * 2 + ff];
                    out[o + sdoff] = aS[it][nt][rr * 2 + ff];
                }
            }
}

// ---------------------------------------------------------------------------
extern "C" void kernel_launch(void* const* d_in, const int* in_sizes, int n_in,
                              void* d_out, int out_size) {
    const float* q     = (const float*)d_in[0];
    const float* k     = (const float*)d_in[1];
    const float* v     = (const float*)d_in[2];
    const float* sd    = (const float*)d_in[3];
    const float* table = (const float*)d_in[4];
    const int*   ridx  = (const int*)d_in[5];
    float* out = (float*)d_out;

    const int smem1 = (32 * KSTRIDE + 32 * QSTRIDE + 32 * 16) * (int)sizeof(float); // ~139 KB
    const int smem2 = (128 * PSTRIDE + 2 * 32 * VSTRIDE) * (int)sizeof(float);      // ~53 KB
    cudaFuncSetAttribute(scores_mma_kernel, cudaFuncAttributeMaxDynamicSharedMemorySize, smem1);
    cudaFuncSetAttribute(out_mma_kernel,    cudaFuncAttributeMaxDynamicSharedMemorySize, smem2);

    bias_kernel<<<(LDIM * LDIM) / 256, 256>>>(table, ridx);
    scores_mma_kernel<<<dim3(LDIM / 32, BATCH), T1, smem1>>>(q, k);
    out_mma_kernel<<<dim3(LDIM / 128, CDIM / 128, BATCH), T2, smem2>>>(v, sd, out);
}

// round 6
// speedup vs baseline: 1.0014x; 1.0014x over previous
#include <cuda_runtime.h>

#define BATCH 32
#define CDIM  256
#define LDIM  1024

// Scratch: softmax probabilities P[B][L][L] fp32 (128 MiB) + dense bias [L][L].
__device__ float d_P[(size_t)BATCH * LDIM * LDIM];
__device__ float d_bias[(size_t)LDIM * LDIM];

// ---------------------------------------------------------------------------
// tf32 mma.sync helpers
// ---------------------------------------------------------------------------
__device__ __forceinline__ void mma8(float* c,
                                     unsigned a0, unsigned a1, unsigned a2, unsigned a3,
                                     unsigned b0, unsigned b1) {
    asm volatile(
        "mma.sync.aligned.m16n8k8.row.col.f32.tf32.tf32.f32 "
        "{%0,%1,%2,%3}, {%4,%5,%6,%7}, {%8,%9}, {%0,%1,%2,%3};\n"
        : "+f"(c[0]), "+f"(c[1]), "+f"(c[2]), "+f"(c[3])
        : "r"(a0), "r"(a1), "r"(a2), "r"(a3), "r"(b0), "r"(b1));
}

__device__ __forceinline__ unsigned tf32_hi(float x) {
    return __float_as_uint(x) & 0xffffe000u;
}
__device__ __forceinline__ unsigned tf32_lo(float x, unsigned hi) {
    return __float_as_uint(x - __uint_as_float(hi));
}
__device__ __forceinline__ unsigned tf32_rna(float x) {
    unsigned r;
    asm("cvt.rna.tf32.f32 %0, %1;" : "=r"(r) : "f"(x));
    return r;
}

// ---------------------------------------------------------------------------
// Kernel 0: expand bias_table[rel_index] -> dense [L,L]
// ---------------------------------------------------------------------------
__global__ void bias_kernel(const float* __restrict__ table,
                            const int* __restrict__ ridx) {
    int i = blockIdx.x * blockDim.x + threadIdx.x;
    d_bias[i] = table[ridx[i]];
}

// ---------------------------------------------------------------------------
// Kernel 1: scores = Q^T K + bias (tf32x3 split), softmax over j, write P.
// CTA: 32 i-rows x 1024 j (full row). 512 threads = 16 warps.
// Warp tile: 32i x 64j = 2 i-tiles x 8 j-tiles of m16n8. C chunked by 32.
// smem: ks[32][1032] (pad so B-frag LDS conflict-free), qs[32][36].
// ---------------------------------------------------------------------------
#define T1 512
#define KSTRIDE 1032
#define QSTRIDE 36

__global__ void __launch_bounds__(T1)
scores_mma_kernel(const float* __restrict__ q, const float* __restrict__ k) {
    extern __shared__ float smem[];
    float* ks  = smem;                       // [32][1032]
    float* qs  = smem + 32 * KSTRIDE;        // [32][36]
    float* red = qs + 32 * QSTRIDE;          // [32][16]

    const int b    = blockIdx.y;
    const int i0   = blockIdx.x * 32;
    const int tid  = threadIdx.x;
    const int warp = tid >> 5;
    const int lane = tid & 31;
    const int g    = lane >> 2;              // group row 0..7
    const int tig  = lane & 3;               // thread-in-group
    const int j0w  = warp * 64;

    const float* qb = q + (size_t)b * CDIM * LDIM;
    const float* kb = k + (size_t)b * CDIM * LDIM;

    float acc[2][8][4];
#pragma unroll
    for (int it = 0; it < 2; it++)
#pragma unroll
        for (int jt = 0; jt < 8; jt++)
#pragma unroll
            for (int f = 0; f < 4; f++) acc[it][jt][f] = 0.f;

    for (int c0 = 0; c0 < CDIM; c0 += 32) {
        // K chunk [32][1024] -> ks, coalesced float4
#pragma unroll
        for (int t = 0; t < 16; t++) {
            int idx = tid + t * T1;
            int row = idx >> 8;
            int col = (idx & 255) << 2;
            *(float4*)(ks + row * KSTRIDE + col) =
                *(const float4*)(kb + (size_t)(c0 + row) * LDIM + col);
        }
        // Q chunk: qs[r][cc] = q[c0+cc][i0+r]
#pragma unroll
        for (int t = 0; t < 2; t++) {
            int idx = tid + t * T1;
            int cc = idx >> 5;
            int r  = idx & 31;
            qs[r * QSTRIDE + cc] = qb[(size_t)(c0 + cc) * LDIM + i0 + r];
        }
        __syncthreads();

#pragma unroll
        for (int kk = 0; kk < 32; kk += 8) {
            // A fragments (hi/lo split)
            unsigned ah[2][4], al[2][4];
#pragma unroll
            for (int it = 0; it < 2; it++) {
                int base = (it * 16 + g) * QSTRIDE + kk + tig;
                float a0 = qs[base];
                float a1 = qs[base + 8 * QSTRIDE];
                float a2 = qs[base + 4];
                float a3 = qs[base + 8 * QSTRIDE + 4];
                ah[it][0] = tf32_hi(a0); al[it][0] = tf32_lo(a0, ah[it][0]);
                ah[it][1] = tf32_hi(a1); al[it][1] = tf32_lo(a1, ah[it][1]);
                ah[it][2] = tf32_hi(a2); al[it][2] = tf32_lo(a2, ah[it][2]);
                ah[it][3] = tf32_hi(a3); al[it][3] = tf32_lo(a3, ah[it][3]);
            }
#pragma unroll
            for (int jt = 0; jt < 8; jt++) {
                int jcol = j0w + jt * 8 + g;
                float b0 = ks[(kk + tig) * KSTRIDE + jcol];
                float b1 = ks[(kk + tig + 4) * KSTRIDE + jcol];
                unsigned bh0 = tf32_hi(b0), bh1 = tf32_hi(b1);
                unsigned bl0 = tf32_lo(b0, bh0), bl1 = tf32_lo(b1, bh1);
#pragma unroll
                for (int it = 0; it < 2; it++) {
                    mma8(acc[it][jt], ah[it][0], ah[it][1], ah[it][2], ah[it][3], bh0, bh1);
                    mma8(acc[it][jt], ah[it][0], ah[it][1], ah[it][2], ah[it][3], bl0, bl1);
                    mma8(acc[it][jt], al[it][0], al[it][1], al[it][2], al[it][3], bh0, bh1);
                }
            }
        }
        __syncthreads();
    }

    // ---- add bias ----
#pragma unroll
    for (int it = 0; it < 2; it++)
#pragma unroll
        for (int rr = 0; rr < 2; rr++) {
            int rowl = it * 16 + g + rr * 8;
            const float* brow = d_bias + (size_t)(i0 + rowl) * LDIM + j0w + 2 * tig;
#pragma unroll
            for (int jt = 0; jt < 8; jt++) {
                float2 bv = *(const float2*)(brow + jt * 8);
                acc[it][jt][rr * 2]     += bv.x;
                acc[it][jt][rr * 2 + 1] += bv.y;
            }
        }

    // ---- row max over full 1024 j (16 warps share rows) ----
    float mrow[2][2];
#pragma unroll
    for (int it = 0; it < 2; it++)
#pragma unroll
        for (int rr = 0; rr < 2; rr++) {
            float m = -3.4e38f;
#pragma unroll
            for (int jt = 0; jt < 8; jt++) {
                m = fmaxf(m, acc[it][jt][rr * 2]);
                m = fmaxf(m, acc[it][jt][rr * 2 + 1]);
            }
            m = fmaxf(m, __shfl_xor_sync(0xffffffffu, m, 1));
            m = fmaxf(m, __shfl_xor_sync(0xffffffffu, m, 2));
            if (tig == 0) red[(it * 16 + g + rr * 8) * 16 + warp] = m;
        }
    __syncthreads();
#pragma unroll
    for (int it = 0; it < 2; it++)
#pragma unroll
        for (int rr = 0; rr < 2; rr++) {
            int rowl = it * 16 + g + rr * 8;
            float m = red[rowl * 16];
#pragma unroll
            for (int w = 1; w < 16; w++) m = fmaxf(m, red[rowl * 16 + w]);
            mrow[it][rr] = m;
        }
    __syncthreads();

    // ---- exp + row sum ----
#pragma unroll
    for (int it = 0; it < 2; it++)
#pragma unroll
        for (int rr = 0; rr < 2; rr++) {
            float s = 0.f;
#pragma unroll
            for (int jt = 0; jt < 8; jt++) {
                float p0 = __expf(acc[it][jt][rr * 2]     - mrow[it][rr]);
                float p1 = __expf(acc[it][jt][rr * 2 + 1] - mrow[it][rr]);
                acc[it][jt][rr * 2]     = p0;
                acc[it][jt][rr * 2 + 1] = p1;
                s += p0 + p1;
            }
            s += __shfl_xor_sync(0xffffffffu, s, 1);
            s += __shfl_xor_sync(0xffffffffu, s, 2);
            if (tig == 0) red[(it * 16 + g + rr * 8) * 16 + warp] = s;
        }
    __syncthreads();

    float* Pb = d_P + ((size_t)b * LDIM + i0) * LDIM;
#pragma unroll
    for (int it = 0; it < 2; it++)
#pragma unroll
        for (int rr = 0; rr < 2; rr++) {
            int rowl = it * 16 + g + rr * 8;
            float s = red[rowl * 16];
#pragma unroll
            for (int w = 1; w < 16; w++) s += red[rowl * 16 + w];
            float inv = 1.0f / s;
            float* prow = Pb + (size_t)rowl * LDIM + j0w + 2 * tig;
#pragma unroll
            for (int jt = 0; jt < 8; jt++) {
                float2 o;
                o.x = acc[it][jt][rr * 2] * inv;
                o.y = acc[it][jt][rr * 2 + 1] * inv;
                *(float2*)(prow + jt * 8) = o;
            }
        }
}

// ---------------------------------------------------------------------------
// Kernel 2: V = P @ v^T, SD = P @ std^T, single-pass tf32 mma.
// CTA tile: 128i x 128c. 512 threads = 16 warps (4 wi x 4 wc).
// Warp tile: 32i x 32c = 2 i-tiles x 4 n-tiles per output.
// Operands pre-converted to tf32 (rna) when staged into smem.
// ---------------------------------------------------------------------------
#define T2 512
#define PSTRIDE 36
#define VSTRIDE 136

__global__ void __launch_bounds__(T2)
out_mma_kernel(const float* __restrict__ v, const float* __restrict__ sd,
               float* __restrict__ out) {
    extern __shared__ float smem2[];
    float* ps = smem2;                        // [128][36]
    float* vs = ps + 128 * PSTRIDE;           // [32][136]
    float* ss = vs + 32 * VSTRIDE;            // [32][136]

    const int b    = blockIdx.z;
    const int i0   = blockIdx.x * 128;
    const int c0   = blockIdx.y * 128;
    const int tid  = threadIdx.x;
    const int warp = tid >> 5;
    const int lane = tid & 31;
    const int g    = lane >> 2;
    const int tig  = lane & 3;
    const int wi   = warp & 3;                // i block of 32
    const int wc   = warp >> 2;               // c block of 32

    const float* Pb = d_P + ((size_t)b * LDIM + i0) * LDIM;
    const float* vb = v  + ((size_t)b * CDIM + c0) * LDIM;
    const float* sb = sd + ((size_t)b * CDIM + c0) * LDIM;

    float aV[2][4][4], aS[2][4][4];
#pragma unroll
    for (int it = 0; it < 2; it++)
#pragma unroll
        for (int nt = 0; nt < 4; nt++)
#pragma unroll
            for (int f = 0; f < 4; f++) { aV[it][nt][f] = 0.f; aS[it][nt][f] = 0.f; }

    for (int j0 = 0; j0 < LDIM; j0 += 32) {
        // P tile 128 x 32 (row-major, pre-cvt to tf32)
#pragma unroll
        for (int t = 0; t < 2; t++) {
            int idx = tid + t * T2;
            int i  = idx >> 3;
            int j4 = (idx & 7) << 2;
            float4 p4 = *(const float4*)(Pb + (size_t)i * LDIM + j0 + j4);
            float* dst = ps + i * PSTRIDE + j4;
            dst[0] = __uint_as_float(tf32_rna(p4.x));
            dst[1] = __uint_as_float(tf32_rna(p4.y));
            dst[2] = __uint_as_float(tf32_rna(p4.z));
            dst[3] = __uint_as_float(tf32_rna(p4.w));
        }
        // v / std tiles 128c x 32j -> transposed [j][c], pre-cvt
#pragma unroll
        for (int t = 0; t < 2; t++) {
            int idx = tid + t * T2;
            int c  = idx >> 3;
            int j4 = (idx & 7) << 2;
            float4 t4 = *(const float4*)(vb + (size_t)c * LDIM + j0 + j4);
            vs[(j4 + 0) * VSTRIDE + c] = __uint_as_float(tf32_rna(t4.x));
            vs[(j4 + 1) * VSTRIDE + c] = __uint_as_float(tf32_rna(t4.y));
            vs[(j4 + 2) * VSTRIDE + c] = __uint_as_float(tf32_rna(t4.z));
            vs[(j4 + 3) * VSTRIDE + c] = __uint_as_float(tf32_rna(t4.w));
            float4 u4 = *(const float4*)(sb + (size_t)c * LDIM + j0 + j4);
            ss[(j4 + 0) * VSTRIDE + c] = __uint_as_float(tf32_rna(u4.x));
            ss[(j4 + 1) * VSTRIDE + c] = __uint_as_float(tf32_rna(u4.y));
            ss[(j4 + 2) * VSTRIDE + c] = __uint_as_float(tf32_rna(u4.z));
            ss[(j4 + 3) * VSTRIDE + c] = __uint_as_float(tf32_rna(u4.w));
        }
        __syncthreads();

#pragma unroll
        for (int kk = 0; kk < 32; kk += 8) {
            unsigned au[2][4];
#pragma unroll
            for (int it = 0; it < 2; it++) {
                int base = (wi * 32 + it * 16 + g) * PSTRIDE + kk + tig;
                au[it][0] = __float_as_uint(ps[base]);
                au[it][1] = __float_as_uint(ps[base + 8 * PSTRIDE]);
                au[it][2] = __float_as_uint(ps[base + 4]);
                au[it][3] = __float_as_uint(ps[base + 8 * PSTRIDE + 4]);
            }
#pragma unroll
            for (int nt = 0; nt < 4; nt++) {
                int ncol = wc * 32 + nt * 8 + g;
                unsigned bv0 = __float_as_uint(vs[(kk + tig) * VSTRIDE + ncol]);
                unsigned bv1 = __float_as_uint(vs[(kk + tig + 4) * VSTRIDE + ncol]);
                unsigned bs0 = __float_as_uint(ss[(kk + tig) * VSTRIDE + ncol]);
                unsigned bs1 = __float_as_uint(ss[(kk + tig + 4) * VSTRIDE + ncol]);
#pragma unroll
                for (int it = 0; it < 2; it++) {
                    mma8(aV[it][nt], au[it][0], au[it][1], au[it][2], au[it][3], bv0, bv1);
                    mma8(aS[it][nt], au[it][0], au[it][1], au[it][2], au[it][3], bs0, bs1);
                }
            }
        }
        __syncthreads();
    }

    // epilogue: out[b][c][i] for V, then SD at +B*C*L
    const size_t base  = (size_t)b * CDIM * LDIM;
    const size_t sdoff = (size_t)BATCH * CDIM * LDIM;
#pragma unroll
    for (int it = 0; it < 2; it++)
#pragma unroll
        for (int nt = 0; nt < 4; nt++)
#pragma unroll
            for (int rr = 0; rr < 2; rr++) {
                int i = i0 + wi * 32 + it * 16 + g + rr * 8;
#pragma unroll
                for (int ff = 0; ff < 2; ff++) {
                    int c = c0 + wc * 32 + nt * 8 + 2 * tig + ff;
                    size_t o = base + (size_t)c * LDIM + i;
                    out[o]         = aV[it][nt][rr * 2 + ff];
                    out[o + sdoff] = aS[it][nt][rr * 2 + ff];
                }
            }
}

// ---------------------------------------------------------------------------
extern "C" void kernel_launch(void* const* d_in, const int* in_sizes, int n_in,
                              void* d_out, int out_size) {
    const float* q     = (const float*)d_in[0];
    const float* k     = (const float*)d_in[1];
    const float* v     = (const float*)d_in[2];
    const float* sd    = (const float*)d_in[3];
    const float* table = (const float*)d_in[4];
    const int*   ridx  = (const int*)d_in[5];
    float* out = (float*)d_out;

    const int smem1 = (32 * KSTRIDE + 32 * QSTRIDE + 32 * 16) * (int)sizeof(float); // ~139 KB
    const int smem2 = (128 * PSTRIDE + 2 * 32 * VSTRIDE) * (int)sizeof(float);      // ~53 KB
    cudaFuncSetAttribute(scores_mma_kernel, cudaFuncAttributeMaxDynamicSharedMemorySize, smem1);
    cudaFuncSetAttribute(out_mma_kernel,    cudaFuncAttributeMaxDynamicSharedMemorySize, smem2);

    bias_kernel<<<(LDIM * LDIM) / 256, 256>>>(table, ridx);
    scores_mma_kernel<<<dim3(LDIM / 32, BATCH), T1, smem1>>>(q, k);
    out_mma_kernel<<<dim3(LDIM / 128, CDIM / 128, BATCH), T2, smem2>>>(v, sd, out);
}

// round 7
// speedup vs baseline: 1.5399x; 1.5377x over previous
#include <cuda_runtime.h>
#include <cuda_fp16.h>

#define BATCH 32
#define CDIM  256
#define LDIM  1024

// ---------------------------------------------------------------------------
// Global scratch (pair-packed fp16 operands + half2 P + dense bias)
// q/k packed: [b][m][i], m = c/2, uint2 = (hi2, lo2), hi2 = (half(x[2m][i]), half(x[2m+1][i]))
// v/std packed: [b][c][j2], uint = half2(v[c][2j2], v[c][2j2+1])
// P packed: [b][i][j2], uint = half2(P[i][2j2], P[i][2j2+1])
// ---------------------------------------------------------------------------
__device__ uint2    d_qpk[(size_t)BATCH * (CDIM / 2) * LDIM];      // 32 MiB
__device__ uint2    d_kpk[(size_t)BATCH * (CDIM / 2) * LDIM];      // 32 MiB
__device__ unsigned d_vpk[(size_t)BATCH * CDIM * (LDIM / 2)];      // 16 MiB
__device__ unsigned d_spk[(size_t)BATCH * CDIM * (LDIM / 2)];      // 16 MiB
__device__ unsigned d_Ph [(size_t)BATCH * LDIM * (LDIM / 2)];      // 64 MiB
__device__ float    d_bias[(size_t)LDIM * LDIM];                   //  4 MiB

__device__ __forceinline__ unsigned pk2(__half a, __half b) {
    __half2 t = __halves2half2(a, b);
    return *reinterpret_cast<unsigned*>(&t);
}

__device__ __forceinline__ void mma16(float* c,
                                      unsigned a0, unsigned a1, unsigned a2, unsigned a3,
                                      unsigned b0, unsigned b1) {
    asm volatile(
        "mma.sync.aligned.m16n8k16.row.col.f32.f16.f16.f32 "
        "{%0,%1,%2,%3}, {%4,%5,%6,%7}, {%8,%9}, {%0,%1,%2,%3};\n"
        : "+f"(c[0]), "+f"(c[1]), "+f"(c[2]), "+f"(c[3])
        : "r"(a0), "r"(a1), "r"(a2), "r"(a3), "r"(b0), "r"(b1));
}

// ---------------------------------------------------------------------------
// Pack kernels
// ---------------------------------------------------------------------------
__global__ void pack_qk(const float* __restrict__ q, const float* __restrict__ k) {
    int gid = blockIdx.x * 256 + threadIdx.x;        // over B * 128 * 1024
    int b   = gid >> 17;
    int rem = gid & 131071;
    int m   = rem >> 10;
    int i   = rem & 1023;
    size_t src = (size_t)b * CDIM * LDIM + (size_t)(2 * m) * LDIM + i;

    float x0 = q[src], x1 = q[src + LDIM];
    __half h0 = __float2half_rn(x0), h1 = __float2half_rn(x1);
    __half l0 = __float2half_rn(x0 - __half2float(h0));
    __half l1 = __float2half_rn(x1 - __half2float(h1));
    d_qpk[gid] = make_uint2(pk2(h0, h1), pk2(l0, l1));

    float y0 = k[src], y1 = k[src + LDIM];
    __half g0 = __float2half_rn(y0), g1 = __float2half_rn(y1);
    __half m0 = __float2half_rn(y0 - __half2float(g0));
    __half m1 = __float2half_rn(y1 - __half2float(g1));
    d_kpk[gid] = make_uint2(pk2(g0, g1), pk2(m0, m1));
}

__global__ void pack_vs(const float* __restrict__ v, const float* __restrict__ sd) {
    int gid = blockIdx.x * 256 + threadIdx.x;        // over B * 256 * 512
    size_t src = (size_t)gid * 2;
    float2 t = *(const float2*)(v + src);
    d_vpk[gid] = pk2(__float2half_rn(t.x), __float2half_rn(t.y));
    float2 u = *(const float2*)(sd + src);
    d_spk[gid] = pk2(__float2half_rn(u.x), __float2half_rn(u.y));
}

__global__ void bias_kernel(const float* __restrict__ table,
                            const int* __restrict__ ridx) {
    int i = blockIdx.x * blockDim.x + threadIdx.x;
    d_bias[i] = table[ridx[i]];
}

// ---------------------------------------------------------------------------
// Kernel 1: scores = Q^T K + bias (fp16x2 3-pass), softmax, P -> half2.
// CTA: 32 i x 1024 j, 512 threads = 16 warps, warp tile 32i x 64j.
// smem strides (words mod 32): ks 2*1028=2056==8, qs 2*36=72==8 -> frag-load conflict-free.
// ---------------------------------------------------------------------------
#define T1  512
#define KS2 1028   // uint2 stride, 16 rows (c-pairs) x 1024 j
#define QS2 36     // uint2 stride, qs[m][i] : 16 x 32

__global__ void __launch_bounds__(T1)
scores_kernel(void) {
    extern __shared__ unsigned char smraw[];
    uint2* ks = (uint2*)smraw;                                 // [16][1028]
    uint2* qs = ks + 16 * KS2;                                 // [16][36]
    float* red = (float*)(qs + 16 * QS2);                      // [32][16]

    const int b    = blockIdx.y;
    const int i0   = blockIdx.x * 32;
    const int tid  = threadIdx.x;
    const int warp = tid >> 5;
    const int lane = tid & 31;
    const int g    = lane >> 2;
    const int tig  = lane & 3;
    const int j0w  = warp * 64;

    const uint2* gq = d_qpk + (size_t)b * (CDIM / 2) * LDIM;
    const uint2* gk = d_kpk + (size_t)b * (CDIM / 2) * LDIM;

    float acc[2][8][4];
#pragma unroll
    for (int it = 0; it < 2; it++)
#pragma unroll
        for (int jt = 0; jt < 8; jt++)
#pragma unroll
            for (int f = 0; f < 4; f++) acc[it][jt][f] = 0.f;

    for (int cc = 0; cc < 8; cc++) {                 // c chunk of 32 (16 pair-rows)
        // K chunk: 16 x 1024 uint2 via uint4 (8192 uint4, 16/thread)
        const uint4* src4 = (const uint4*)(gk + (size_t)cc * 16 * LDIM);
#pragma unroll
        for (int t = 0; t < 16; t++) {
            int idx  = tid + t * T1;
            int row  = idx >> 9;
            int col4 = idx & 511;
            *(uint4*)((unsigned char*)ks + row * (KS2 * 8) + col4 * 16) = src4[idx];
        }
        // Q chunk: 16 x 32 uint2, qs[m][i]
        {
            int m = tid >> 5;
            int i = tid & 31;
            qs[m * QS2 + i] = gq[(size_t)(cc * 16 + m) * LDIM + i0 + i];
        }
        __syncthreads();

#pragma unroll
        for (int kk2 = 0; kk2 < 16; kk2 += 8) {      // two k16 blocks per chunk
            uint2 a0[2], a1[2], a2[2], a3[2];
#pragma unroll
            for (int it = 0; it < 2; it++) {
                int r = it * 16 + g;
                a0[it] = qs[(kk2 + tig) * QS2 + r];
                a1[it] = qs[(kk2 + tig) * QS2 + r + 8];
                a2[it] = qs[(kk2 + tig + 4) * QS2 + r];
                a3[it] = qs[(kk2 + tig + 4) * QS2 + r + 8];
            }
#pragma unroll
            for (int jt = 0; jt < 8; jt++) {
                int jcol = j0w + jt * 8 + g;
                uint2 y0 = ks[(kk2 + tig) * KS2 + jcol];
                uint2 y1 = ks[(kk2 + tig + 4) * KS2 + jcol];
#pragma unroll
                for (int it = 0; it < 2; it++) {
                    mma16(acc[it][jt], a0[it].x, a1[it].x, a2[it].x, a3[it].x, y0.x, y1.x); // hi*hi
                    mma16(acc[it][jt], a0[it].x, a1[it].x, a2[it].x, a3[it].x, y0.y, y1.y); // hi*lo
                    mma16(acc[it][jt], a0[it].y, a1[it].y, a2[it].y, a3[it].y, y0.x, y1.x); // lo*hi
                }
            }
        }
        __syncthreads();
    }

    // ---- add bias ----
#pragma unroll
    for (int it = 0; it < 2; it++)
#pragma unroll
        for (int rr = 0; rr < 2; rr++) {
            int rowl = it * 16 + g + rr * 8;
            const float* brow = d_bias + (size_t)(i0 + rowl) * LDIM + j0w + 2 * tig;
#pragma unroll
            for (int jt = 0; jt < 8; jt++) {
                float2 bv = *(const float2*)(brow + jt * 8);
                acc[it][jt][rr * 2]     += bv.x;
                acc[it][jt][rr * 2 + 1] += bv.y;
            }
        }

    // ---- row max ----
    float mrow[2][2];
#pragma unroll
    for (int it = 0; it < 2; it++)
#pragma unroll
        for (int rr = 0; rr < 2; rr++) {
            float m = -3.4e38f;
#pragma unroll
            for (int jt = 0; jt < 8; jt++) {
                m = fmaxf(m, acc[it][jt][rr * 2]);
                m = fmaxf(m, acc[it][jt][rr * 2 + 1]);
            }
            m = fmaxf(m, __shfl_xor_sync(0xffffffffu, m, 1));
            m = fmaxf(m, __shfl_xor_sync(0xffffffffu, m, 2));
            if (tig == 0) red[(it * 16 + g + rr * 8) * 16 + warp] = m;
        }
    __syncthreads();
#pragma unroll
    for (int it = 0; it < 2; it++)
#pragma unroll
        for (int rr = 0; rr < 2; rr++) {
            int rowl = it * 16 + g + rr * 8;
            float m = red[rowl * 16];
#pragma unroll
            for (int w = 1; w < 16; w++) m = fmaxf(m, red[rowl * 16 + w]);
            mrow[it][rr] = m;
        }
    __syncthreads();

    // ---- exp + row sum ----
#pragma unroll
    for (int it = 0; it < 2; it++)
#pragma unroll
        for (int rr = 0; rr < 2; rr++) {
            float s = 0.f;
#pragma unroll
            for (int jt = 0; jt < 8; jt++) {
                float p0 = __expf(acc[it][jt][rr * 2]     - mrow[it][rr]);
                float p1 = __expf(acc[it][jt][rr * 2 + 1] - mrow[it][rr]);
                acc[it][jt][rr * 2]     = p0;
                acc[it][jt][rr * 2 + 1] = p1;
                s += p0 + p1;
            }
            s += __shfl_xor_sync(0xffffffffu, s, 1);
            s += __shfl_xor_sync(0xffffffffu, s, 2);
            if (tig == 0) red[(it * 16 + g + rr * 8) * 16 + warp] = s;
        }
    __syncthreads();

    unsigned* Pb = d_Ph + ((size_t)b * LDIM + i0) * (LDIM / 2);
#pragma unroll
    for (int it = 0; it < 2; it++)
#pragma unroll
        for (int rr = 0; rr < 2; rr++) {
            int rowl = it * 16 + g + rr * 8;
            float s = red[rowl * 16];
#pragma unroll
            for (int w = 1; w < 16; w++) s += red[rowl * 16 + w];
            float inv = 1.0f / s;
            unsigned* prow = Pb + (size_t)rowl * (LDIM / 2) + j0w / 2 + tig;
#pragma unroll
            for (int jt = 0; jt < 8; jt++) {
                __half2 h = __floats2half2_rn(acc[it][jt][rr * 2] * inv,
                                              acc[it][jt][rr * 2 + 1] * inv);
                prow[jt * 4] = *reinterpret_cast<unsigned*>(&h);
            }
        }
}

// ---------------------------------------------------------------------------
// Kernel 2: V = P @ v^T, SD = P @ std^T, fp16 single-pass m16n8k16.
// CTA tile: 128i x 128c, 512 threads = 16 warps (4 wi x 4 wc), j chunk 64.
// smem strides (words mod 32): ps 36==4, vs/ss 136==8 -> frag loads conflict-free.
// ---------------------------------------------------------------------------
#define T2  512
#define PSU 36
#define VSU 136

__global__ void __launch_bounds__(T2)
out_kernel(float* __restrict__ out) {
    extern __shared__ unsigned char smraw2[];
    unsigned* ps = (unsigned*)smraw2;          // [128][36]
    unsigned* vs = ps + 128 * PSU;             // [32][136]
    unsigned* ss = vs + 32 * VSU;              // [32][136]

    const int b    = blockIdx.z;
    const int i0   = blockIdx.x * 128;
    const int c0   = blockIdx.y * 128;
    const int tid  = threadIdx.x;
    const int warp = tid >> 5;
    const int lane = tid & 31;
    const int g    = lane >> 2;
    const int tig  = lane & 3;
    const int wi   = warp & 3;
    const int wc   = warp >> 2;

    const unsigned* Pb = d_Ph + ((size_t)b * LDIM + i0) * (LDIM / 2);
    const unsigned* vb = d_vpk + ((size_t)b * CDIM + c0) * (LDIM / 2);
    const unsigned* sb = d_spk + ((size_t)b * CDIM + c0) * (LDIM / 2);

    float aV[2][4][4], aS[2][4][4];
#pragma unroll
    for (int it = 0; it < 2; it++)
#pragma unroll
        for (int nt = 0; nt < 4; nt++)
#pragma unroll
            for (int f = 0; f < 4; f++) { aV[it][nt][f] = 0.f; aS[it][nt][f] = 0.f; }

    for (int j2 = 0; j2 < LDIM / 2; j2 += 32) {          // j chunk of 64
        // P tile: 128 x 32 uint via uint4 (1024 uint4, 2/thread)
#pragma unroll
        for (int t = 0; t < 2; t++) {
            int idx  = tid + t * T2;
            int row  = idx >> 3;
            int col4 = idx & 7;
            uint4 p4 = *(const uint4*)(Pb + (size_t)row * (LDIM / 2) + j2 + col4 * 4);
            *(uint4*)((unsigned char*)ps + row * (PSU * 4) + col4 * 16) = p4;
        }
        // v/std tiles: 128c x 32j2 -> transposed [j2][c]
#pragma unroll
        for (int t = 0; t < 4; t++) {
            int idx = tid + t * T2;
            int c   = idx >> 4;
            int mp  = idx & 15;
            uint2 tv = *(const uint2*)(vb + (size_t)c * (LDIM / 2) + j2 + 2 * mp);
            vs[(2 * mp) * VSU + c]     = tv.x;
            vs[(2 * mp + 1) * VSU + c] = tv.y;
            uint2 ts = *(const uint2*)(sb + (size_t)c * (LDIM / 2) + j2 + 2 * mp);
            ss[(2 * mp) * VSU + c]     = ts.x;
            ss[(2 * mp + 1) * VSU + c] = ts.y;
        }
        __syncthreads();

#pragma unroll
        for (int kk2 = 0; kk2 < 32; kk2 += 8) {
            unsigned a0[2], a1[2], a2[2], a3[2];
#pragma unroll
            for (int it = 0; it < 2; it++) {
                int r = wi * 32 + it * 16 + g;
                a0[it] = ps[r * PSU + kk2 + tig];
                a1[it] = ps[(r + 8) * PSU + kk2 + tig];
                a2[it] = ps[r * PSU + kk2 + tig + 4];
                a3[it] = ps[(r + 8) * PSU + kk2 + tig + 4];
            }
#pragma unroll
            for (int nt = 0; nt < 4; nt++) {
                int ncol = wc * 32 + nt * 8 + g;
                unsigned bv0 = vs[(kk2 + tig) * VSU + ncol];
                unsigned bv1 = vs[(kk2 + tig + 4) * VSU + ncol];
                unsigned bs0 = ss[(kk2 + tig) * VSU + ncol];
                unsigned bs1 = ss[(kk2 + tig + 4) * VSU + ncol];
#pragma unroll
                for (int it = 0; it < 2; it++) {
                    mma16(aV[it][nt], a0[it], a1[it], a2[it], a3[it], bv0, bv1);
                    mma16(aS[it][nt], a0[it], a1[it], a2[it], a3[it], bs0, bs1);
                }
            }
        }
        __syncthreads();
    }

    const size_t base  = (size_t)b * CDIM * LDIM;
    const size_t sdoff = (size_t)BATCH * CDIM * LDIM;
#pragma unroll
    for (int it = 0; it < 2; it++)
#pragma unroll
        for (int nt = 0; nt < 4; nt++)
#pragma unroll
            for (int rr = 0; rr < 2; rr++) {
                int i = i0 + wi * 32 + it * 16 + g + rr * 8;
#pragma unroll
                for (int ff = 0; ff < 2; ff++) {
                    int c = c0 + wc * 32 + nt * 8 + 2 * tig + ff;
                    size_t o = base + (size_t)c * LDIM + i;
                    out[o]         = aV[it][nt][rr * 2 + ff];
                    out[o + sdoff] = aS[it][nt][rr * 2 + ff];
                }
            }
}

// ---------------------------------------------------------------------------
extern "C" void kernel_launch(void* const* d_in, const int* in_sizes, int n_in,
                              void* d_out, int out_size) {
    const float* q     = (const float*)d_in[0];
    const float* k     = (const float*)d_in[1];
    const float* v     = (const float*)d_in[2];
    const float* sd    = (const float*)d_in[3];
    const float* table = (const float*)d_in[4];
    const int*   ridx  = (const int*)d_in[5];
    float* out = (float*)d_out;

    const int smem1 = (16 * KS2 + 16 * QS2) * 8 + 32 * 16 * 4;   // ~139 KB
    const int smem2 = (128 * PSU + 2 * 32 * VSU) * 4;            // ~52 KB
    cudaFuncSetAttribute(scores_kernel, cudaFuncAttributeMaxDynamicSharedMemorySize, smem1);
    cudaFuncSetAttribute(out_kernel,    cudaFuncAttributeMaxDynamicSharedMemorySize, smem2);

    pack_qk<<<(BATCH * (CDIM / 2) * LDIM) / 256, 256>>>(q, k);
    pack_vs<<<(BATCH * CDIM * (LDIM / 2)) / 256, 256>>>(v, sd);
    bias_kernel<<<(LDIM * LDIM) / 256, 256>>>(table, ridx);
    scores_kernel<<<dim3(LDIM / 32, BATCH), T1, smem1>>>();
    out_kernel<<<dim3(LDIM / 128, CDIM / 128, BATCH), T2, smem2>>>(out);
}

// round 8
// speedup vs baseline: 2.1244x; 1.3796x over previous
#include <cuda_runtime.h>
#include <cuda_fp16.h>

#define BATCH 32
#define CDIM  256
#define LDIM  1024

// ---------------------------------------------------------------------------
// Global scratch (pair-packed fp16 operands + half2 P + dense bias)
// q/k packed: [b][m][i], m = c/2, uint2 = (hi2, lo2), hi2 = (half(x[2m][i]), half(x[2m+1][i]))
// v/std packed: [b][c][j2], uint = half2(v[c][2j2], v[c][2j2+1])
// P packed: [b][i][j2], uint = half2(P[i][2j2], P[i][2j2+1])
// ---------------------------------------------------------------------------
__device__ uint2    d_qpk[(size_t)BATCH * (CDIM / 2) * LDIM];      // 32 MiB
__device__ uint2    d_kpk[(size_t)BATCH * (CDIM / 2) * LDIM];      // 32 MiB
__device__ unsigned d_vpk[(size_t)BATCH * CDIM * (LDIM / 2)];      // 16 MiB
__device__ unsigned d_spk[(size_t)BATCH * CDIM * (LDIM / 2)];      // 16 MiB
__device__ unsigned d_Ph [(size_t)BATCH * LDIM * (LDIM / 2)];      // 64 MiB
__device__ float    d_bias[(size_t)LDIM * LDIM];                   //  4 MiB

__device__ __forceinline__ unsigned pk2(__half a, __half b) {
    __half2 t = __halves2half2(a, b);
    return *reinterpret_cast<unsigned*>(&t);
}

__device__ __forceinline__ void mma16(float* c,
                                      unsigned a0, unsigned a1, unsigned a2, unsigned a3,
                                      unsigned b0, unsigned b1) {
    asm volatile(
        "mma.sync.aligned.m16n8k16.row.col.f32.f16.f16.f32 "
        "{%0,%1,%2,%3}, {%4,%5,%6,%7}, {%8,%9}, {%0,%1,%2,%3};\n"
        : "+f"(c[0]), "+f"(c[1]), "+f"(c[2]), "+f"(c[3])
        : "r"(a0), "r"(a1), "r"(a2), "r"(a3), "r"(b0), "r"(b1));
}

__device__ __forceinline__ void ldsm4(unsigned& r0, unsigned& r1,
                                      unsigned& r2, unsigned& r3, unsigned a) {
    asm volatile("ldmatrix.sync.aligned.m8n8.x4.shared.b16 {%0,%1,%2,%3}, [%4];"
                 : "=r"(r0), "=r"(r1), "=r"(r2), "=r"(r3) : "r"(a));
}

__device__ __forceinline__ void cp16(unsigned dst, const void* src) {
    asm volatile("cp.async.cg.shared.global [%0], [%1], 16;" :: "r"(dst), "l"(src));
}
#define CP_COMMIT() asm volatile("cp.async.commit_group;")
#define CP_WAIT(N)  asm volatile("cp.async.wait_group %0;" :: "n"(N))

// ---------------------------------------------------------------------------
// Pack kernels
// ---------------------------------------------------------------------------
__global__ void pack_qk(const float* __restrict__ q, const float* __restrict__ k) {
    int gid = blockIdx.x * 256 + threadIdx.x;
    int b   = gid >> 17;
    int rem = gid & 131071;
    int m   = rem >> 10;
    int i   = rem & 1023;
    size_t src = (size_t)b * CDIM * LDIM + (size_t)(2 * m) * LDIM + i;

    float x0 = q[src], x1 = q[src + LDIM];
    __half h0 = __float2half_rn(x0), h1 = __float2half_rn(x1);
    __half l0 = __float2half_rn(x0 - __half2float(h0));
    __half l1 = __float2half_rn(x1 - __half2float(h1));
    d_qpk[gid] = make_uint2(pk2(h0, h1), pk2(l0, l1));

    float y0 = k[src], y1 = k[src + LDIM];
    __half g0 = __float2half_rn(y0), g1 = __float2half_rn(y1);
    __half m0 = __float2half_rn(y0 - __half2float(g0));
    __half m1 = __float2half_rn(y1 - __half2float(g1));
    d_kpk[gid] = make_uint2(pk2(g0, g1), pk2(m0, m1));
}

__global__ void pack_vs(const float* __restrict__ v, const float* __restrict__ sd) {
    int gid = blockIdx.x * 256 + threadIdx.x;
    size_t src = (size_t)gid * 2;
    float2 t = *(const float2*)(v + src);
    d_vpk[gid] = pk2(__float2half_rn(t.x), __float2half_rn(t.y));
    float2 u = *(const float2*)(sd + src);
    d_spk[gid] = pk2(__float2half_rn(u.x), __float2half_rn(u.y));
}

__global__ void bias_kernel(const float* __restrict__ table,
                            const int* __restrict__ ridx) {
    int i = blockIdx.x * blockDim.x + threadIdx.x;
    d_bias[i] = table[ridx[i]];
}

// ---------------------------------------------------------------------------
// Kernel 1: scores = Q^T K + bias (fp16x2 3-pass), softmax, P -> half2.
// CTA: 32 i x 1024 j, 512 threads = 16 warps, warp tile 32i x 64j.
// c chunked by 16 (8 pair-rows), 16 chunks, double-buffered via cp.async.
// ks: [buf][8][KS2] uint2, rows = c-pairs; A: qh/ql [buf][32][12] uints, ldmatrix.
// Pass-outer mma ordering: dependent mmas separated by 8 independent ones.
// ---------------------------------------------------------------------------
#define T1  512
#define KS2 1028
#define QSW 12

// smem byte offsets
#define SC_KS(buf)   ((buf) * (8 * KS2 * 8))
#define SC_QH(buf)   (2 * 8 * KS2 * 8 + (buf) * (32 * QSW * 4))
#define SC_QL(buf)   (2 * 8 * KS2 * 8 + 2 * (32 * QSW * 4) + (buf) * (32 * QSW * 4))
#define SC_RED       (2 * 8 * KS2 * 8 + 4 * (32 * QSW * 4))
#define SC_TOTAL     (SC_RED + 32 * 16 * 4)

__global__ void __launch_bounds__(T1)
scores_kernel(void) {
    extern __shared__ unsigned char smraw[];
    const unsigned sbase = (unsigned)__cvta_generic_to_shared(smraw);

    const int b    = blockIdx.y;
    const int i0   = blockIdx.x * 32;
    const int tid  = threadIdx.x;
    const int warp = tid >> 5;
    const int lane = tid & 31;
    const int g    = lane >> 2;
    const int tig  = lane & 3;
    const int j0w  = warp * 64;

    const uint2* gq = d_qpk + (size_t)b * (CDIM / 2) * LDIM;
    const uint2* gk = d_kpk + (size_t)b * (CDIM / 2) * LDIM;

    float acc[2][8][4];
#pragma unroll
    for (int it = 0; it < 2; it++)
#pragma unroll
        for (int jt = 0; jt < 8; jt++)
#pragma unroll
            for (int f = 0; f < 4; f++) acc[it][jt][f] = 0.f;

    // ---- staging (macro so it is inlined twice: prologue + loop tail) ----
#define SC_STAGE(CC, BUF)                                                     \
    {                                                                         \
        const uint4* src4 = (const uint4*)(gk + (size_t)(CC) * 8 * LDIM);     \
        unsigned ksb = sbase + SC_KS(BUF);                                    \
        _Pragma("unroll")                                                     \
        for (int t = 0; t < 8; t++) {                                         \
            int idx  = tid + t * T1;                                          \
            int row  = idx >> 9;                                              \
            int col4 = idx & 511;                                             \
            cp16(ksb + row * (KS2 * 8) + col4 * 16, src4 + idx);              \
        }                                                                     \
        if (tid < 256) {                                                      \
            int m = tid >> 5, ii = tid & 31;                                  \
            uint2 qv = gq[(size_t)((CC) * 8 + m) * LDIM + i0 + ii];           \
            *(unsigned*)(smraw + SC_QH(BUF) + (ii * QSW + m) * 4) = qv.x;     \
            *(unsigned*)(smraw + SC_QL(BUF) + (ii * QSW + m) * 4) = qv.y;     \
        }                                                                     \
        CP_COMMIT();                                                          \
    }

    SC_STAGE(0, 0);
    SC_STAGE(1, 1);

    for (int cc = 0; cc < 16; cc++) {
        if (cc < 15) { CP_WAIT(1); } else { CP_WAIT(0); }
        __syncthreads();

        const int buf = cc & 1;
        // A fragments via ldmatrix.x4 (hi and lo)
        unsigned ah[2][4], al[2][4];
        const unsigned arow = (lane & 15);
        const unsigned acol = (lane >> 4) * 16;
#pragma unroll
        for (int it = 0; it < 2; it++) {
            ldsm4(ah[it][0], ah[it][1], ah[it][2], ah[it][3],
                  sbase + SC_QH(buf) + (it * 16 + arow) * (QSW * 4) + acol);
            ldsm4(al[it][0], al[it][1], al[it][2], al[it][3],
                  sbase + SC_QL(buf) + (it * 16 + arow) * (QSW * 4) + acol);
        }
        const uint2* ksb = (const uint2*)(smraw + SC_KS(buf));
#pragma unroll
        for (int jh = 0; jh < 2; jh++) {
            uint2 y0[4], y1[4];
#pragma unroll
            for (int j4 = 0; j4 < 4; j4++) {
                int jcol = j0w + (jh * 4 + j4) * 8 + g;
                y0[j4] = ksb[tig * KS2 + jcol];
                y1[j4] = ksb[(tig + 4) * KS2 + jcol];
            }
            // pass 1: hi*hi
#pragma unroll
            for (int j4 = 0; j4 < 4; j4++)
#pragma unroll
                for (int it = 0; it < 2; it++)
                    mma16(acc[it][jh * 4 + j4], ah[it][0], ah[it][1], ah[it][2], ah[it][3],
                          y0[j4].x, y1[j4].x);
            // pass 2: hi*lo
#pragma unroll
            for (int j4 = 0; j4 < 4; j4++)
#pragma unroll
                for (int it = 0; it < 2; it++)
                    mma16(acc[it][jh * 4 + j4], ah[it][0], ah[it][1], ah[it][2], ah[it][3],
                          y0[j4].y, y1[j4].y);
            // pass 3: lo*hi
#pragma unroll
            for (int j4 = 0; j4 < 4; j4++)
#pragma unroll
                for (int it = 0; it < 2; it++)
                    mma16(acc[it][jh * 4 + j4], al[it][0], al[it][1], al[it][2], al[it][3],
                          y0[j4].x, y1[j4].x);
        }
        __syncthreads();
        if (cc + 2 < 16) SC_STAGE(cc + 2, buf);
    }

    float* red = (float*)(smraw + SC_RED);

    // ---- add bias ----
#pragma unroll
    for (int it = 0; it < 2; it++)
#pragma unroll
        for (int rr = 0; rr < 2; rr++) {
            int rowl = it * 16 + g + rr * 8;
            const float* brow = d_bias + (size_t)(i0 + rowl) * LDIM + j0w + 2 * tig;
#pragma unroll
            for (int jt = 0; jt < 8; jt++) {
                float2 bv = *(const float2*)(brow + jt * 8);
                acc[it][jt][rr * 2]     += bv.x;
                acc[it][jt][rr * 2 + 1] += bv.y;
            }
        }

    // ---- row max ----
    float mrow[2][2];
#pragma unroll
    for (int it = 0; it < 2; it++)
#pragma unroll
        for (int rr = 0; rr < 2; rr++) {
            float m = -3.4e38f;
#pragma unroll
            for (int jt = 0; jt < 8; jt++) {
                m = fmaxf(m, acc[it][jt][rr * 2]);
                m = fmaxf(m, acc[it][jt][rr * 2 + 1]);
            }
            m = fmaxf(m, __shfl_xor_sync(0xffffffffu, m, 1));
            m = fmaxf(m, __shfl_xor_sync(0xffffffffu, m, 2));
            if (tig == 0) red[(it * 16 + g + rr * 8) * 16 + warp] = m;
        }
    __syncthreads();
#pragma unroll
    for (int it = 0; it < 2; it++)
#pragma unroll
        for (int rr = 0; rr < 2; rr++) {
            int rowl = it * 16 + g + rr * 8;
            float m = red[rowl * 16];
#pragma unroll
            for (int w = 1; w < 16; w++) m = fmaxf(m, red[rowl * 16 + w]);
            mrow[it][rr] = m;
        }
    __syncthreads();

    // ---- exp + row sum ----
#pragma unroll
    for (int it = 0; it < 2; it++)
#pragma unroll
        for (int rr = 0; rr < 2; rr++) {
            float s = 0.f;
#pragma unroll
            for (int jt = 0; jt < 8; jt++) {
                float p0 = __expf(acc[it][jt][rr * 2]     - mrow[it][rr]);
                float p1 = __expf(acc[it][jt][rr * 2 + 1] - mrow[it][rr]);
                acc[it][jt][rr * 2]     = p0;
                acc[it][jt][rr * 2 + 1] = p1;
                s += p0 + p1;
            }
            s += __shfl_xor_sync(0xffffffffu, s, 1);
            s += __shfl_xor_sync(0xffffffffu, s, 2);
            if (tig == 0) red[(it * 16 + g + rr * 8) * 16 + warp] = s;
        }
    __syncthreads();

    unsigned* Pb = d_Ph + ((size_t)b * LDIM + i0) * (LDIM / 2);
#pragma unroll
    for (int it = 0; it < 2; it++)
#pragma unroll
        for (int rr = 0; rr < 2; rr++) {
            int rowl = it * 16 + g + rr * 8;
            float s = red[rowl * 16];
#pragma unroll
            for (int w = 1; w < 16; w++) s += red[rowl * 16 + w];
            float inv = 1.0f / s;
            unsigned* prow = Pb + (size_t)rowl * (LDIM / 2) + j0w / 2 + tig;
#pragma unroll
            for (int jt = 0; jt < 8; jt++) {
                __half2 h = __floats2half2_rn(acc[it][jt][rr * 2] * inv,
                                              acc[it][jt][rr * 2 + 1] * inv);
                prow[jt * 4] = *reinterpret_cast<unsigned*>(&h);
            }
        }
}

// ---------------------------------------------------------------------------
// Kernel 2: V = P @ v^T, SD = P @ std^T, fp16 m16n8k16, ldmatrix everywhere.
// CTA tile: 128i x 128c, 512 threads = 16 warps (4 wi x 4 wc), j chunk 64.
// Natural [c][j] smem layout for v/std (NO transpose); B frags via non-trans
// ldmatrix.x4. Double-buffered cp.async staging (2 x 55.3 KB).
// ---------------------------------------------------------------------------
#define T2  512
#define OSW 36   // uints per smem row (144 B, 16B-aligned, 4-bank row offset)

#define OC_PS(buf)  ((buf) * (3 * 128 * OSW * 4))
#define OC_VS(buf)  (OC_PS(buf) + 128 * OSW * 4)
#define OC_SS(buf)  (OC_PS(buf) + 2 * 128 * OSW * 4)
#define OC_TOTAL    (2 * 3 * 128 * OSW * 4)

__global__ void __launch_bounds__(T2)
out_kernel(float* __restrict__ out) {
    extern __shared__ unsigned char smraw2[];
    const unsigned sbase = (unsigned)__cvta_generic_to_shared(smraw2);

    const int b    = blockIdx.z;
    const int i0   = blockIdx.x * 128;
    const int c0   = blockIdx.y * 128;
    const int tid  = threadIdx.x;
    const int warp = tid >> 5;
    const int lane = tid & 31;
    const int g    = lane >> 2;
    const int tig  = lane & 3;
    const int wi   = warp & 3;
    const int wc   = warp >> 2;

    const unsigned* Pb = d_Ph + ((size_t)b * LDIM + i0) * (LDIM / 2);
    const unsigned* vb = d_vpk + ((size_t)b * CDIM + c0) * (LDIM / 2);
    const unsigned* sb = d_spk + ((size_t)b * CDIM + c0) * (LDIM / 2);

    float aV[2][4][4], aS[2][4][4];
#pragma unroll
    for (int it = 0; it < 2; it++)
#pragma unroll
        for (int nt = 0; nt < 4; nt++)
#pragma unroll
            for (int f = 0; f < 4; f++) { aV[it][nt][f] = 0.f; aS[it][nt][f] = 0.f; }

#define OC_STAGE(JC, BUF)                                                     \
    {                                                                         \
        _Pragma("unroll")                                                     \
        for (int t = 0; t < 2; t++) {                                         \
            int idx  = tid + t * T2;                                          \
            int row  = idx >> 3;                                              \
            int col4 = idx & 7;                                               \
            unsigned soff = row * (OSW * 4) + col4 * 16;                      \
            size_t   goff = (size_t)row * (LDIM / 2) + (JC) * 32 + col4 * 4;  \
            cp16(sbase + OC_PS(BUF) + soff, Pb + goff);                       \
            cp16(sbase + OC_VS(BUF) + soff, vb + goff);                       \
            cp16(sbase + OC_SS(BUF) + soff, sb + goff);                       \
        }                                                                     \
        CP_COMMIT();                                                          \
    }

    OC_STAGE(0, 0);
    OC_STAGE(1, 1);

    // ldmatrix address components (lane-dependent, loop-invariant)
    const unsigned a_row  = (lane & 15);
    const unsigned a_col  = (lane >> 4) * 16;
    const unsigned b_row  = ((lane >> 4) & 1) * 8 + (lane & 7);
    const unsigned b_col  = ((lane >> 3) & 1) * 16;

    for (int jc = 0; jc < 16; jc++) {
        if (jc < 15) { CP_WAIT(1); } else { CP_WAIT(0); }
        __syncthreads();
        const int buf = jc & 1;

#pragma unroll
        for (int kb = 0; kb < 4; kb++) {
            unsigned a0[2], a1[2], a2[2], a3[2];
#pragma unroll
            for (int it = 0; it < 2; it++)
                ldsm4(a0[it], a1[it], a2[it], a3[it],
                      sbase + OC_PS(buf) +
                      (wi * 32 + it * 16 + a_row) * (OSW * 4) + kb * 32 + a_col);

            unsigned bv0[4], bv1[4], bs0[4], bs1[4];
#pragma unroll
            for (int nh = 0; nh < 2; nh++) {
                unsigned roff = (wc * 32 + nh * 16 + b_row) * (OSW * 4) + kb * 32 + b_col;
                ldsm4(bv0[2 * nh], bv1[2 * nh], bv0[2 * nh + 1], bv1[2 * nh + 1],
                      sbase + OC_VS(buf) + roff);
                ldsm4(bs0[2 * nh], bs1[2 * nh], bs0[2 * nh + 1], bs1[2 * nh + 1],
                      sbase + OC_SS(buf) + roff);
            }
#pragma unroll
            for (int nt = 0; nt < 4; nt++)
#pragma unroll
                for (int it = 0; it < 2; it++) {
                    mma16(aV[it][nt], a0[it], a1[it], a2[it], a3[it], bv0[nt], bv1[nt]);
                    mma16(aS[it][nt], a0[it], a1[it], a2[it], a3[it], bs0[nt], bs1[nt]);
                }
        }
        __syncthreads();
        if (jc + 2 < 16) OC_STAGE(jc + 2, buf);
    }

    const size_t base  = (size_t)b * CDIM * LDIM;
    const size_t sdoff = (size_t)BATCH * CDIM * LDIM;
#pragma unroll
    for (int it = 0; it < 2; it++)
#pragma unroll
        for (int nt = 0; nt < 4; nt++)
#pragma unroll
            for (int rr = 0; rr < 2; rr++) {
                int i = i0 + wi * 32 + it * 16 + g + rr * 8;
#pragma unroll
                for (int ff = 0; ff < 2; ff++) {
                    int c = c0 + wc * 32 + nt * 8 + 2 * tig + ff;
                    size_t o = base + (size_t)c * LDIM + i;
                    out[o]         = aV[it][nt][rr * 2 + ff];
                    out[o + sdoff] = aS[it][nt][rr * 2 + ff];
                }
            }
}

// ---------------------------------------------------------------------------
extern "C" void kernel_launch(void* const* d_in, const int* in_sizes, int n_in,
                              void* d_out, int out_size) {
    const float* q     = (const float*)d_in[0];
    const float* k     = (const float*)d_in[1];
    const float* v     = (const float*)d_in[2];
    const float* sd    = (const float*)d_in[3];
    const float* table = (const float*)d_in[4];
    const int*   ridx  = (const int*)d_in[5];
    float* out = (float*)d_out;

    cudaFuncSetAttribute(scores_kernel, cudaFuncAttributeMaxDynamicSharedMemorySize, SC_TOTAL);
    cudaFuncSetAttribute(out_kernel,    cudaFuncAttributeMaxDynamicSharedMemorySize, OC_TOTAL);

    pack_qk<<<(BATCH * (CDIM / 2) * LDIM) / 256, 256>>>(q, k);
    pack_vs<<<(BATCH * CDIM * (LDIM / 2)) / 256, 256>>>(v, sd);
    bias_kernel<<<(LDIM * LDIM) / 256, 256>>>(table, ridx);
    scores_kernel<<<dim3(LDIM / 32, BATCH), T1, SC_TOTAL>>>();
    out_kernel<<<dim3(LDIM / 128, CDIM / 128, BATCH), T2, OC_TOTAL>>>(out);
}